// round 15
// baseline (speedup 1.0000x reference)
#include <cuda_runtime.h>
#include <cstdint>

#define NSEG   10000
#define D      128
#define BM     72
#define BLK_B  576
#define XS_STRIDE 132
#define NBLK_G ((NSEG + BM - 1) / BM)     // 139
#define SMEM_B ((D * D + BM * XS_STRIDE) * 4)   // 103552 bytes

__device__ float g_sums[NSEG * D];

// graph may be int32 or int64 depending on jax x64 config.
// int32 layout: word[2*NSEG-1] = ends[NSEG-1] = N-1 (nonzero).
// int64 layout: word[2*NSEG-1] = high half of element NSEG-1 -> 0.
__device__ __forceinline__ void load_seg(const int* __restrict__ g, int s,
                                         int& st, int& en) {
    bool is64 = (g[2 * NSEG - 1] == 0);
    if (is64) { st = g[4 * s];  en = g[4 * s + 2]; }
    else      { st = g[2 * s];  en = g[2 * s + 1]; }
}

// ---------------------------------------------------------------------------
// Kernel 1: block-per-segment sum (R7 body — protected). NEW: PDL trigger
// at block start so the gemm can launch (and stage W) during the sum's
// final wave instead of after full completion.
// ---------------------------------------------------------------------------
__global__ void __launch_bounds__(128) sum_kernel(
    const float* __restrict__ input,
    const int*   __restrict__ graph)
{
    cudaTriggerProgrammaticLaunchCompletion();

    const int s    = blockIdx.x;
    const int c4   = threadIdx.x & 31;   // float4 column within row
    const int rl   = threadIdx.x >> 5;   // warp id 0..3

    int start, end;
    load_seg(graph, s, start, end);
    const int n = end - start + 1;

    const float4* base = (const float4*)input + (long long)start * 32 + c4;

    float4 acc = make_float4(0.f, 0.f, 0.f, 0.f);
    int r = rl;
    for (; r + 12 < n; r += 16) {
        const float4* p = base + (long long)r * 32;
        float4 v0 = p[0 * 32];
        float4 v1 = p[4 * 32];
        float4 v2 = p[8 * 32];
        float4 v3 = p[12 * 32];
        acc.x += (v0.x + v1.x) + (v2.x + v3.x);
        acc.y += (v0.y + v1.y) + (v2.y + v3.y);
        acc.z += (v0.z + v1.z) + (v2.z + v3.z);
        acc.w += (v0.w + v1.w) + (v2.w + v3.w);
    }
    for (; r < n; r += 4) {
        float4 v = base[(long long)r * 32];
        acc.x += v.x; acc.y += v.y; acc.z += v.z; acc.w += v.w;
    }

    __shared__ float4 red[4][32];
    red[rl][c4] = acc;
    __syncthreads();
    if (rl == 0) {
        float4 a = red[0][c4], b2 = red[1][c4], c = red[2][c4], d = red[3][c4];
        float4 t;
        t.x = (a.x + b2.x) + (c.x + d.x);
        t.y = (a.y + b2.y) + (c.y + d.y);
        t.z = (a.z + b2.z) + (c.z + d.z);
        t.w = (a.w + b2.w) + (c.w + d.w);
        ((float4*)g_sums)[s * 32 + c4] = t;
    }
}

// ---------------------------------------------------------------------------
// Kernel 2: out[m][n] = sum_k xs[m][k] * WT[k][n] + cnt_m * b[n]
// R7 tiling (BM=72, 576 thr, 139 blocks = one wave, conflict-free n-split).
// NEW: explicit register double-buffer on the W tile — w(k+1) loads issue
// before the 16 FFMAs of k, hiding the 29-cyc LDS latency at 4.5 warps/SMSP.
// ---------------------------------------------------------------------------
__global__ void __launch_bounds__(BLK_B) seg_gemm_kernel(
    const int*   __restrict__ graph,
    const float* __restrict__ W,
    const float* __restrict__ b,
    float*       __restrict__ out)
{
    extern __shared__ float sm[];
    float* ws = sm;            // ws[k*D + n]  (transposed W, 64KB)
    float* xs = sm + D * D;    // xs[m*XS_STRIDE + k]

    const int tid = threadIdx.x;
    const int m0  = blockIdx.x * BM;

    // Overlapped prologue (PDL): transpose W into ws. Independent of sum.
    for (int lin = tid; lin < D * D / 4; lin += BLK_B) {
        int j = lin >> 7;          // 0..31
        int n = lin & 127;
        float4 w = ((const float4*)W)[n * 32 + j];
        ws[(4 * j + 0) * D + n] = w.x;
        ws[(4 * j + 1) * D + n] = w.y;
        ws[(4 * j + 2) * D + n] = w.z;
        ws[(4 * j + 3) * D + n] = w.w;
    }

    // Gate only the g_sums consumption on the sum kernel.
    cudaGridDependencySynchronize();

    // Stage x tile (72 rows x 32 float4 = 2304 = 4 * 576).
    {
#pragma unroll
        for (int i = 0; i < (BM * D / 4) / BLK_B; i++) {   // 4 iters
            int lin = tid + i * BLK_B;
            int m   = lin >> 5;
            int k4  = lin & 31;
            int seg = m0 + m;
            float4 v = make_float4(0.f, 0.f, 0.f, 0.f);
            if (seg < NSEG) v = ((const float4*)g_sums)[seg * 32 + k4];
            *(float4*)(xs + m * XS_STRIDE + k4 * 4) = v;
        }
    }
    __syncthreads();

    const int tx = tid & 15;    // n-groups: [tx*4, +4) and [64+tx*4, +4)
    const int ty = tid >> 4;    // m-group: m = ty*2, ty*2+1  (ty 0..35)

    float acc[2][8];
#pragma unroll
    for (int i = 0; i < 2; i++)
#pragma unroll
        for (int j = 0; j < 8; j++) acc[i][j] = 0.f;

    const float* xp0 = xs + (ty * 2 + 0) * XS_STRIDE;
    const float* xp1 = xs + (ty * 2 + 1) * XS_STRIDE;
    const float* wp  = ws + tx * 4;

    // Software-pipelined mainloop: W for k+1 in flight during FFMAs of k.
    // The k=128 prefetch over-reads into xs (valid smem, value unused).
    float4 w0 = *(const float4*)(wp);
    float4 w1 = *(const float4*)(wp + 64);

#pragma unroll 2
    for (int k = 0; k < D; k += 4) {
        float4 xv0 = *(const float4*)(xp0 + k);
        float4 xv1 = *(const float4*)(xp1 + k);
        const float xr0[4] = {xv0.x, xv0.y, xv0.z, xv0.w};
        const float xr1[4] = {xv1.x, xv1.y, xv1.z, xv1.w};
#pragma unroll
        for (int kk = 0; kk < 4; kk++) {
            float4 nw0 = *(const float4*)(wp + (k + kk + 1) * D);
            float4 nw1 = *(const float4*)(wp + (k + kk + 1) * D + 64);

            float x0 = xr0[kk];
            float x1 = xr1[kk];
            acc[0][0] += x0 * w0.x; acc[0][1] += x0 * w0.y;
            acc[0][2] += x0 * w0.z; acc[0][3] += x0 * w0.w;
            acc[0][4] += x0 * w1.x; acc[0][5] += x0 * w1.y;
            acc[0][6] += x0 * w1.z; acc[0][7] += x0 * w1.w;

            acc[1][0] += x1 * w0.x; acc[1][1] += x1 * w0.y;
            acc[1][2] += x1 * w0.z; acc[1][3] += x1 * w0.w;
            acc[1][4] += x1 * w1.x; acc[1][5] += x1 * w1.y;
            acc[1][6] += x1 * w1.z; acc[1][7] += x1 * w1.w;

            w0 = nw0;
            w1 = nw1;
        }
    }

    // Epilogue: + count * b. Two coalesced float4 groups at n=tx*4, 64+tx*4.
    float4 b0 = ((const float4*)b)[tx];
    float4 b1 = ((const float4*)b)[16 + tx];

#pragma unroll
    for (int i = 0; i < 2; i++) {
        int seg = m0 + ty * 2 + i;
        if (seg >= NSEG) continue;
        int st, en;
        load_seg(graph, seg, st, en);
        float cnt = (float)(en - st + 1);

        float4 o0, o1;
        o0.x = acc[i][0] + cnt * b0.x;
        o0.y = acc[i][1] + cnt * b0.y;
        o0.z = acc[i][2] + cnt * b0.z;
        o0.w = acc[i][3] + cnt * b0.w;
        o1.x = acc[i][4] + cnt * b1.x;
        o1.y = acc[i][5] + cnt * b1.y;
        o1.z = acc[i][6] + cnt * b1.z;
        o1.w = acc[i][7] + cnt * b1.w;

        float* op = out + (long long)seg * D;
        *(float4*)(op + tx * 4)      = o0;
        *(float4*)(op + 64 + tx * 4) = o1;
    }
}

extern "C" void kernel_launch(void* const* d_in, const int* in_sizes, int n_in,
                              void* d_out, int out_size) {
    const float* input = (const float*)d_in[0];
    const int*   graph = (const int*)  d_in[1];
    const float* W     = (const float*)d_in[2];
    const float* b     = (const float*)d_in[3];
    float*       out   = (float*)d_out;

    cudaFuncSetAttribute(seg_gemm_kernel,
                         cudaFuncAttributeMaxDynamicSharedMemorySize, SMEM_B);

    sum_kernel<<<NSEG, 128>>>(input, graph);

    // PDL launch: gemm prologue overlaps the sum kernel's last wave.
    cudaLaunchConfig_t cfg = {};
    cfg.gridDim          = dim3(NBLK_G, 1, 1);
    cfg.blockDim         = dim3(BLK_B, 1, 1);
    cfg.dynamicSmemBytes = SMEM_B;
    cfg.stream           = 0;
    cudaLaunchAttribute attrs[1];
    attrs[0].id = cudaLaunchAttributeProgrammaticStreamSerialization;
    attrs[0].val.programmaticStreamSerializationAllowed = 1;
    cfg.attrs    = attrs;
    cfg.numAttrs = 1;
    cudaLaunchKernelEx(&cfg, seg_gemm_kernel, graph, W, b, out);
}

// round 16
// speedup vs baseline: 1.1861x; 1.1861x over previous
#include <cuda_runtime.h>
#include <cstdint>

#define NSEG   10000
#define D      128
#define BM     72
#define BLK_B  576
#define XS_STRIDE 132
#define NBLK_G ((NSEG + BM - 1) / BM)     // 139
#define SMEM_B ((D * D + BM * XS_STRIDE) * 4)   // 103552 bytes

__device__ float g_sumsA[NSEG * D];   // first-half partial sums
__device__ float g_sumsB[NSEG * D];   // second-half partial sums

// graph may be int32 or int64 depending on jax x64 config.
// int32 layout: word[2*NSEG-1] = ends[NSEG-1] = N-1 (nonzero).
// int64 layout: word[2*NSEG-1] = high half of element NSEG-1 -> 0.
__device__ __forceinline__ void load_seg(const int* __restrict__ g, int s,
                                         int& st, int& en) {
    bool is64 = (g[2 * NSEG - 1] == 0);
    if (is64) { st = g[4 * s];  en = g[4 * s + 2]; }
    else      { st = g[2 * s];  en = g[2 * s + 1]; }
}

// ---------------------------------------------------------------------------
// Kernel 1: TWO blocks per segment (halves the straggler tail). Block
// bid = 2*s + h streams half h of segment s with the R7 pattern (warp rl
// takes rows rl+16i+{0,4,8,12}, 4 LDG.128 in flight, one sync at the end)
// and writes its partial to g_sumsA/g_sumsB. No atomics, no memset — the
// gemm adds the two halves while staging.
// ---------------------------------------------------------------------------
__global__ void __launch_bounds__(128) sum_kernel(
    const float* __restrict__ input,
    const int*   __restrict__ graph)
{
    const int s    = blockIdx.x >> 1;
    const int h    = blockIdx.x & 1;
    const int c4   = threadIdx.x & 31;   // float4 column within row
    const int rl   = threadIdx.x >> 5;   // warp id 0..3

    int start, end;
    load_seg(graph, s, start, end);
    const int nfull = end - start + 1;
    const int n0    = (nfull + 1) >> 1;

    // This block's half-range.
    const int hstart = h ? (start + n0) : start;
    const int n      = h ? (nfull - n0) : n0;
    float* dst = (h ? g_sumsB : g_sumsA) + s * D;

    float4 acc = make_float4(0.f, 0.f, 0.f, 0.f);
    if (n > 0) {
        const float4* base = (const float4*)input + (long long)hstart * 32 + c4;
        int r = rl;
        for (; r + 12 < n; r += 16) {
            const float4* p = base + (long long)r * 32;
            float4 v0 = p[0 * 32];
            float4 v1 = p[4 * 32];
            float4 v2 = p[8 * 32];
            float4 v3 = p[12 * 32];
            acc.x += (v0.x + v1.x) + (v2.x + v3.x);
            acc.y += (v0.y + v1.y) + (v2.y + v3.y);
            acc.z += (v0.z + v1.z) + (v2.z + v3.z);
            acc.w += (v0.w + v1.w) + (v2.w + v3.w);
        }
        for (; r < n; r += 4) {
            float4 v = base[(long long)r * 32];
            acc.x += v.x; acc.y += v.y; acc.z += v.z; acc.w += v.w;
        }
    }

    __shared__ float4 red[4][32];
    red[rl][c4] = acc;
    __syncthreads();
    if (rl == 0) {
        float4 a = red[0][c4], b2 = red[1][c4], c = red[2][c4], d = red[3][c4];
        float4 t;
        t.x = (a.x + b2.x) + (c.x + d.x);
        t.y = (a.y + b2.y) + (c.y + d.y);
        t.z = (a.z + b2.z) + (c.z + d.z);
        t.w = (a.w + b2.w) + (c.w + d.w);
        ((float4*)dst)[c4] = t;
    }
}

// ---------------------------------------------------------------------------
// Kernel 2: out[m][n] = sum_k xs[m][k] * WT[k][n] + cnt_m * b[n]
// R7 mainloop (protected, 47 regs). PDL (no early trigger): W-transpose
// prologue independent of the sum; g_sums reads gated by
// cudaGridDependencySynchronize. xs staging adds the two half-buffers.
// ---------------------------------------------------------------------------
__global__ void __launch_bounds__(BLK_B) seg_gemm_kernel(
    const int*   __restrict__ graph,
    const float* __restrict__ W,
    const float* __restrict__ b,
    float*       __restrict__ out)
{
    extern __shared__ float sm[];
    float* ws = sm;            // ws[k*D + n]  (transposed W, 64KB)
    float* xs = sm + D * D;    // xs[m*XS_STRIDE + k]

    const int tid = threadIdx.x;
    const int m0  = blockIdx.x * BM;

    // Prologue: transpose W into ws (independent of the sum kernel).
    for (int lin = tid; lin < D * D / 4; lin += BLK_B) {
        int j = lin >> 7;          // 0..31
        int n = lin & 127;
        float4 w = ((const float4*)W)[n * 32 + j];
        ws[(4 * j + 0) * D + n] = w.x;
        ws[(4 * j + 1) * D + n] = w.y;
        ws[(4 * j + 2) * D + n] = w.z;
        ws[(4 * j + 3) * D + n] = w.w;
    }

    cudaGridDependencySynchronize();

    // Stage x tile: sum of the two halves.
    {
#pragma unroll
        for (int i = 0; i < (BM * D / 4) / BLK_B; i++) {   // 4 iters
            int lin = tid + i * BLK_B;
            int m   = lin >> 5;
            int k4  = lin & 31;
            int seg = m0 + m;
            float4 v = make_float4(0.f, 0.f, 0.f, 0.f);
            if (seg < NSEG) {
                float4 a = ((const float4*)g_sumsA)[seg * 32 + k4];
                float4 c = ((const float4*)g_sumsB)[seg * 32 + k4];
                v.x = a.x + c.x; v.y = a.y + c.y;
                v.z = a.z + c.z; v.w = a.w + c.w;
            }
            *(float4*)(xs + m * XS_STRIDE + k4 * 4) = v;
        }
    }
    __syncthreads();

    const int tx = tid & 15;    // n-groups: [tx*4, +4) and [64+tx*4, +4)
    const int ty = tid >> 4;    // m-group: m = ty*2, ty*2+1  (ty 0..35)

    float acc[2][8];
#pragma unroll
    for (int i = 0; i < 2; i++)
#pragma unroll
        for (int j = 0; j < 8; j++) acc[i][j] = 0.f;

    const float* xp0 = xs + (ty * 2 + 0) * XS_STRIDE;
    const float* xp1 = xs + (ty * 2 + 1) * XS_STRIDE;
    const float* wp  = ws + tx * 4;

#pragma unroll 2
    for (int k = 0; k < D; k += 4) {
        float4 xv0 = *(const float4*)(xp0 + k);
        float4 xv1 = *(const float4*)(xp1 + k);
        const float xr[2][4] = {
            {xv0.x, xv0.y, xv0.z, xv0.w},
            {xv1.x, xv1.y, xv1.z, xv1.w},
        };
#pragma unroll
        for (int kk = 0; kk < 4; kk++) {
            float4 w0 = *(const float4*)(wp + (k + kk) * D);
            float4 w1 = *(const float4*)(wp + (k + kk) * D + 64);
#pragma unroll
            for (int i = 0; i < 2; i++) {
                float x = xr[i][kk];
                acc[i][0] += x * w0.x; acc[i][1] += x * w0.y;
                acc[i][2] += x * w0.z; acc[i][3] += x * w0.w;
                acc[i][4] += x * w1.x; acc[i][5] += x * w1.y;
                acc[i][6] += x * w1.z; acc[i][7] += x * w1.w;
            }
        }
    }

    // Epilogue: + count * b. Two coalesced float4 groups at n=tx*4, 64+tx*4.
    float4 b0 = ((const float4*)b)[tx];
    float4 b1 = ((const float4*)b)[16 + tx];

#pragma unroll
    for (int i = 0; i < 2; i++) {
        int seg = m0 + ty * 2 + i;
        if (seg >= NSEG) continue;
        int st, en;
        load_seg(graph, seg, st, en);
        float cnt = (float)(en - st + 1);

        float4 o0, o1;
        o0.x = acc[i][0] + cnt * b0.x;
        o0.y = acc[i][1] + cnt * b0.y;
        o0.z = acc[i][2] + cnt * b0.z;
        o0.w = acc[i][3] + cnt * b0.w;
        o1.x = acc[i][4] + cnt * b1.x;
        o1.y = acc[i][5] + cnt * b1.y;
        o1.z = acc[i][6] + cnt * b1.z;
        o1.w = acc[i][7] + cnt * b1.w;

        float* op = out + (long long)seg * D;
        *(float4*)(op + tx * 4)      = o0;
        *(float4*)(op + 64 + tx * 4) = o1;
    }
}

extern "C" void kernel_launch(void* const* d_in, const int* in_sizes, int n_in,
                              void* d_out, int out_size) {
    const float* input = (const float*)d_in[0];
    const int*   graph = (const int*)  d_in[1];
    const float* W     = (const float*)d_in[2];
    const float* b     = (const float*)d_in[3];
    float*       out   = (float*)d_out;

    cudaFuncSetAttribute(seg_gemm_kernel,
                         cudaFuncAttributeMaxDynamicSharedMemorySize, SMEM_B);

    sum_kernel<<<2 * NSEG, 128>>>(input, graph);

    // PDL launch (no early trigger — R15 lesson): prologue overlaps only
    // the natural launch latency; g_sums reads gated inside the kernel.
    cudaLaunchConfig_t cfg = {};
    cfg.gridDim          = dim3(NBLK_G, 1, 1);
    cfg.blockDim         = dim3(BLK_B, 1, 1);
    cfg.dynamicSmemBytes = SMEM_B;
    cfg.stream           = 0;
    cudaLaunchAttribute attrs[1];
    attrs[0].id = cudaLaunchAttributeProgrammaticStreamSerialization;
    attrs[0].val.programmaticStreamSerializationAllowed = 1;
    cfg.attrs    = attrs;
    cfg.numAttrs = 1;
    cudaLaunchKernelEx(&cfg, seg_gemm_kernel, graph, W, b, out);
}